// round 15
// baseline (speedup 1.0000x reference)
#include <cuda_runtime.h>
#include <math.h>

// Problem constants
constexpr int B_ = 8, N_ = 2048, F_ = 128, H_ = 128, O_ = 64;
constexpr int ROWS = B_ * N_;            // 16384
constexpr float NEG_INF = -1.0e9f;

// Output layout (tuple flattened in order)
constexpr long long OFF_XPROJ  = 0;
constexpr long long OFF_LOGITS = OFF_XPROJ  + (long long)B_ * N_ * O_;
constexpr long long OFF_ADJ1   = OFF_LOGITS + (long long)B_ * N_ * O_;
constexpr long long OFF_EYE    = OFF_ADJ1   + (long long)N_ * N_;
constexpr long long OFF_Z      = OFF_EYE    + (long long)N_ * N_;
constexpr long long OFF_ZPOS   = OFF_Z      + 1;                    // odd -> 4B only
constexpr long long OFF_ADJA   = OFF_ZPOS   + (long long)N_ * N_;   // odd
constexpr long long OFF_WA     = OFF_ADJA   + (long long)N_ * N_;

// Scratch (device globals). *t arrays hold tf32 bit patterns.
__device__ unsigned g_hTt  [H_ * ROWS];   // tf32(h^T)       (B-operand k3)
__device__ unsigned g_A1T  [N_ * N_];     // tf32(adj_A1^T)  (A-operand k5)
__device__ unsigned g_xpwTt[O_ * ROWS];   // tf32((xp+Wa)^T) (B-operand k5)
__device__ float    g_es   [ROWS];
__device__ float    g_ed   [ROWS];
__device__ float    g_mx   [ROWS];
__device__ float    g_rs   [ROWS];

// ---- helpers --------------------------------------------------------------
__device__ __forceinline__ unsigned f2tf(float f) {
    unsigned u; asm("cvt.rna.tf32.f32 %0, %1;" : "=r"(u) : "f"(f)); return u;
}
__device__ __forceinline__ void mma8(float* d, const unsigned* a, const unsigned* b) {
    asm volatile("mma.sync.aligned.m16n8k8.row.col.f32.tf32.tf32.f32 "
        "{%0,%1,%2,%3},{%4,%5,%6,%7},{%8,%9},{%0,%1,%2,%3};"
        : "+f"(d[0]), "+f"(d[1]), "+f"(d[2]), "+f"(d[3])
        : "r"(a[0]), "r"(a[1]), "r"(a[2]), "r"(a[3]), "r"(b[0]), "r"(b[1]));
}
__device__ __forceinline__ unsigned smem_u32(const void* p) {
    return (unsigned)__cvta_generic_to_shared(p);
}
__device__ __forceinline__ void ldm_x4(unsigned& r0, unsigned& r1,
                                       unsigned& r2, unsigned& r3, unsigned addr) {
    asm volatile("ldmatrix.sync.aligned.m8n8.x4.shared.b16 {%0,%1,%2,%3}, [%4];"
        : "=r"(r0), "=r"(r1), "=r"(r2), "=r"(r3) : "r"(addr));
}
__device__ __forceinline__ void cp16(unsigned dst, const void* src) {
    asm volatile("cp.async.cg.shared.global [%0], [%1], 16;" :: "r"(dst), "l"(src));
}
#define CP_COMMIT() asm volatile("cp.async.commit_group;")
#define CP_WAIT1()  asm volatile("cp.async.wait_group 1;" ::: "memory")

// fast sinh via exp (rel err ~1e-6, fine vs 1e-3 gate)
__device__ __forceinline__ float fast_sinh(float t) {
    float et = __expf(t);
    return 0.5f * (et - __fdividef(1.f, et));
}

// ---------------------------------------------------------------------------
// K0: elementwise outputs (aligned copies via re-phased float4)
// ---------------------------------------------------------------------------
__global__ void k0_misc(const float* __restrict__ adjA,
                        const float* __restrict__ zpos,
                        const float* __restrict__ Wa,
                        const float* __restrict__ z,
                        float* __restrict__ out)
{
    constexpr int NN = N_ * N_;
    int i4 = blockIdx.x * blockDim.x + threadIdx.x;
    if (i4 < (NN / 4)) {
        int g = i4 * 4;
        float4 a4 = ((const float4*)adjA)[i4];
        const float* ap = (const float*)&a4;

        float4 s4; float* sp = (float*)&s4;
#pragma unroll
        for (int l = 0; l < 4; l++) {
            float c = fminf(fmaxf(ap[l], -3.f), 3.f);
            float s = fast_sinh(3.f * c);
            sp[l] = fminf(fmaxf(s, -1000.f), 1000.f);
        }
        ((float4*)(out + OFF_ADJ1))[i4] = s4;

        int row = g >> 11, col = g & 2047;
        float4 e4; float* ep = (float*)&e4;
#pragma unroll
        for (int l = 0; l < 4; l++) ep[l] = (col + l == row) ? 1.f : 0.f;
        ((float4*)(out + OFF_EYE))[i4] = e4;

        if (i4 < NN / 4 - 1) {
            int d0 = g + 3;
            float4 zc, ac;
            zc.x = zpos[d0];     zc.y = zpos[d0 + 1];
            zc.z = zpos[d0 + 2]; zc.w = zpos[d0 + 3];
            ac.x = adjA[d0];     ac.y = adjA[d0 + 1];
            ac.z = adjA[d0 + 2]; ac.w = adjA[d0 + 3];
            *(float4*)(out + OFF_ZPOS + d0) = zc;
            *(float4*)(out + OFF_ADJA + d0) = ac;
        } else {
            out[OFF_ZPOS + NN - 1] = zpos[NN - 1];
            out[OFF_ADJA + NN - 1] = adjA[NN - 1];
        }
        if (i4 == 0) {
#pragma unroll
            for (int d = 0; d < 3; d++) {
                out[OFF_ZPOS + d] = zpos[d];
                out[OFF_ADJA + d] = adjA[d];
            }
        }
    }
    if (blockIdx.x == 0) {
        if (threadIdx.x < O_)  out[OFF_WA + threadIdx.x] = Wa[threadIdx.x];
        if (threadIdx.x == O_) out[OFF_Z] = z[0];
    }
}

// ---------------------------------------------------------------------------
// K0b: g_A1T = tf32(adj_A1^T)  (32x32 smem tiles)
// ---------------------------------------------------------------------------
__global__ __launch_bounds__(256) void k0b_transpose(const float* __restrict__ out)
{
    __shared__ float t[32][33];
    const float* A1 = out + OFF_ADJ1;
    int bx = blockIdx.x;
    int c0 = (bx & 63) * 32;
    int r0 = (bx >> 6) * 32;
    int tid = threadIdx.x;
    int lr = tid >> 5, lc = tid & 31;
#pragma unroll
    for (int it = 0; it < 4; it++) {
        int row = lr + it * 8;
        t[row][lc] = A1[(long long)(r0 + row) * N_ + c0 + lc];
    }
    __syncthreads();
#pragma unroll
    for (int it = 0; it < 4; it++) {
        int row = lr + it * 8;
        g_A1T[(long long)(c0 + row) * N_ + r0 + lc] = f2tf(t[lc][row]);
    }
}

// ---------------------------------------------------------------------------
// K1: h = x @ W^T -- tf32 mma + fused e_src/e_dst reduction.
// ---------------------------------------------------------------------------
__global__ __launch_bounds__(256) void k1_h(const float* __restrict__ x,
                                            const float* __restrict__ W,
                                            const float* __restrict__ a_src,
                                            const float* __restrict__ a_dst)
{
    __shared__ unsigned sA[64][36];
    __shared__ unsigned sB[128][36];
    __shared__ float eps[4][64], epd[4][64];
    const int m0 = blockIdx.x * 64;
    const int tid = threadIdx.x;
    const int w = tid >> 5, lane = tid & 31;
    const int g = lane >> 2, tg = lane & 3;
    const int mbase = (w >> 2) * 32;
    const int hbase = (w & 3) * 32;
    const int hw = w & 3;

    float acc[2][4][4];
#pragma unroll
    for (int mf = 0; mf < 2; mf++)
#pragma unroll
        for (int nf = 0; nf < 4; nf++)
#pragma unroll
            for (int t = 0; t < 4; t++) acc[mf][nf][t] = 0.f;

    for (int f0 = 0; f0 < F_; f0 += 32) {
#pragma unroll
        for (int it = 0; it < 2; it++) {
            int idx = tid + it * 256;
            int mi = idx >> 3, k4 = idx & 7;
            float4 v = *(const float4*)&x[(m0 + mi) * F_ + f0 + k4 * 4];
            uint4 u = { f2tf(v.x), f2tf(v.y), f2tf(v.z), f2tf(v.w) };
            *(uint4*)&sA[mi][k4 * 4] = u;
        }
#pragma unroll
        for (int it = 0; it < 4; it++) {
            int idx = tid + it * 256;
            int hh = idx >> 3, k4 = idx & 7;
            float4 v = *(const float4*)&W[hh * F_ + f0 + k4 * 4];
            uint4 u = { f2tf(v.x), f2tf(v.y), f2tf(v.z), f2tf(v.w) };
            *(uint4*)&sB[hh][k4 * 4] = u;
        }
        __syncthreads();
#pragma unroll
        for (int ks = 0; ks < 4; ks++) {
            int kb = ks * 8;
            unsigned afr[2][4], bfr[4][2];
#pragma unroll
            for (int mf = 0; mf < 2; mf++) {
                int mr = mbase + mf * 16 + g;
                afr[mf][0] = sA[mr    ][kb + tg];
                afr[mf][1] = sA[mr + 8][kb + tg];
                afr[mf][2] = sA[mr    ][kb + 4 + tg];
                afr[mf][3] = sA[mr + 8][kb + 4 + tg];
            }
#pragma unroll
            for (int nf = 0; nf < 4; nf++) {
                int cc = hbase + nf * 8 + g;
                bfr[nf][0] = sB[cc][kb + tg];
                bfr[nf][1] = sB[cc][kb + 4 + tg];
            }
#pragma unroll
            for (int mf = 0; mf < 2; mf++)
#pragma unroll
                for (int nf = 0; nf < 4; nf++)
                    mma8(acc[mf][nf], afr[mf], bfr[nf]);
        }
        __syncthreads();
    }

    float ps[4] = {0.f, 0.f, 0.f, 0.f};
    float pd[4] = {0.f, 0.f, 0.f, 0.f};
#pragma unroll
    for (int mf = 0; mf < 2; mf++) {
#pragma unroll
        for (int nf = 0; nf < 4; nf++) {
            int c = hbase + nf * 8 + 2 * tg;
            int r0 = m0 + mbase + mf * 16 + g;
            int r1 = r0 + 8;
            float v0 = acc[mf][nf][0], v1 = acc[mf][nf][1];
            float v2 = acc[mf][nf][2], v3 = acc[mf][nf][3];
            g_hTt[(long long)c       * ROWS + r0] = f2tf(v0);
            g_hTt[(long long)(c + 1) * ROWS + r0] = f2tf(v1);
            g_hTt[(long long)c       * ROWS + r1] = f2tf(v2);
            g_hTt[(long long)(c + 1) * ROWS + r1] = f2tf(v3);
            float as0 = a_src[c], as1 = a_src[c + 1];
            float ad0 = a_dst[c], ad1 = a_dst[c + 1];
            ps[mf * 2 + 0] += v0 * as0 + v1 * as1;
            ps[mf * 2 + 1] += v2 * as0 + v3 * as1;
            pd[mf * 2 + 0] += v0 * ad0 + v1 * ad1;
            pd[mf * 2 + 1] += v2 * ad0 + v3 * ad1;
        }
    }
#pragma unroll
    for (int off = 1; off <= 2; off <<= 1) {
#pragma unroll
        for (int s = 0; s < 4; s++) {
            ps[s] += __shfl_xor_sync(0xffffffffu, ps[s], off);
            pd[s] += __shfl_xor_sync(0xffffffffu, pd[s], off);
        }
    }
    if (tg == 0) {
#pragma unroll
        for (int s = 0; s < 4; s++) {
            int row = mbase + (s >> 1) * 16 + g + (s & 1) * 8;
            eps[hw][row] = ps[s];
            epd[hw][row] = pd[s];
        }
    }
    __syncthreads();
    if (tid < 64) {
        float s = eps[0][tid] + eps[1][tid] + eps[2][tid] + eps[3][tid];
        float d = epd[0][tid] + epd[1][tid] + epd[2][tid] + epd[3][tid];
        g_es[m0 + tid] = s;
        g_ed[m0 + tid] = d;
    }
}

// ---------------------------------------------------------------------------
// K2: softmax row stats, vectorized (float4 ed loads, uchar4 mask).
// Pass 1: masked max of raw ed + masked count (lrelu applied post-reduce).
// Pass 2: exp for unmasked; masked handled as cnt*exp(NEG_INF-mx).
// ---------------------------------------------------------------------------
__global__ __launch_bounds__(256) void k2_stats(const float* __restrict__ adjA)
{
    __shared__ unsigned char msk[N_];
    const int m = blockIdx.x;
    const int tid = threadIdx.x;
    const int warp = tid >> 5, lane = tid & 31;

    // mask precompute: float4 adjA loads, uchar4 stores
#pragma unroll
    for (int it = 0; it < 2; it++) {
        int i4 = tid + it * 256;              // 512 float4
        int n = i4 * 4;
        float4 a = *(const float4*)&adjA[(long long)m * N_ + n];
        uchar4 k;
        k.x = (a.x + (n     == m ? 1.f : 0.f) <= 0.f) ? 1 : 0;
        k.y = (a.y + (n + 1 == m ? 1.f : 0.f) <= 0.f) ? 1 : 0;
        k.z = (a.z + (n + 2 == m ? 1.f : 0.f) <= 0.f) ? 1 : 0;
        k.w = (a.w + (n + 3 == m ? 1.f : 0.f) <= 0.f) ? 1 : 0;
        *(uchar4*)&msk[n] = k;
    }
    __syncthreads();

    const int b = warp;
    const int r = b * N_ + m;
    const float es = g_es[r];
    const float* edb = g_ed + b * N_;

    float mxe = -INFINITY;
    int cnt = 0;
#pragma unroll
    for (int t = 0; t < 16; t++) {
        int n = (t * 32 + lane) * 4;
        float4 e = *(const float4*)&edb[n];
        uchar4 k = *(const uchar4*)&msk[n];
        mxe = fmaxf(mxe, k.x ? -INFINITY : e.x);
        mxe = fmaxf(mxe, k.y ? -INFINITY : e.y);
        mxe = fmaxf(mxe, k.z ? -INFINITY : e.z);
        mxe = fmaxf(mxe, k.w ? -INFINITY : e.w);
        cnt += k.x + k.y + k.z + k.w;
    }
#pragma unroll
    for (int off = 16; off >= 1; off >>= 1) {
        mxe = fmaxf(mxe, __shfl_xor_sync(0xffffffffu, mxe, off));
        cnt += __shfl_xor_sync(0xffffffffu, cnt, off);
    }
    float mx;
    if (mxe == -INFINITY) mx = NEG_INF;
    else { float v = es + mxe; mx = fmaxf(v, 0.2f * v); }

    float sm = 0.f;
#pragma unroll
    for (int t = 0; t < 16; t++) {
        int n = (t * 32 + lane) * 4;
        float4 e = *(const float4*)&edb[n];
        uchar4 k = *(const uchar4*)&msk[n];
        float v0 = es + e.x, v1 = es + e.y, v2 = es + e.z, v3 = es + e.w;
        float l0 = fmaxf(v0, 0.2f * v0), l1 = fmaxf(v1, 0.2f * v1);
        float l2 = fmaxf(v2, 0.2f * v2), l3 = fmaxf(v3, 0.2f * v3);
        sm += k.x ? 0.f : __expf(l0 - mx);
        sm += k.y ? 0.f : __expf(l1 - mx);
        sm += k.z ? 0.f : __expf(l2 - mx);
        sm += k.w ? 0.f : __expf(l3 - mx);
    }
#pragma unroll
    for (int off = 16; off >= 1; off >>= 1)
        sm += __shfl_xor_sync(0xffffffffu, sm, off);

    if (lane == 0) {
        sm += (float)cnt * __expf(NEG_INF - mx);
        g_mx[r] = mx;
        g_rs[r] = 1.f / sm;
    }
}

// ---------------------------------------------------------------------------
// K3: hp = elu(attn @ h), then FUSED fc2: x_proj = hp @ fc2w^T + fc2b.
// ---------------------------------------------------------------------------
constexpr int K3_WWORDS = 64 * 36;            // 2304
constexpr int K3_BWORDS = 128 * 36;           // 4608
constexpr int K3_SMEM   = (2 * K3_WWORDS + 3 * K3_BWORDS + 3 * 64) * 4;  // 74496 B

__global__ __launch_bounds__(256) void k3_attn(const float* __restrict__ adjA,
                                               const float* __restrict__ fc2w,
                                               const float* __restrict__ fc2b,
                                               const float* __restrict__ Wa,
                                               float* __restrict__ out)
{
    extern __shared__ unsigned dyn3[];
    unsigned* w_s = dyn3;                       // 2 bufs
    unsigned* sBp = dyn3 + 2 * K3_WWORDS;       // 3 stages
    float* s_mx = (float*)(dyn3 + 2 * K3_WWORDS + 3 * K3_BWORDS);
    float* s_rs = s_mx + 64;
    float* s_es = s_rs + 64;

    const int b  = blockIdx.x >> 5;
    const int m0 = (blockIdx.x & 31) * 64;
    const int rbase = b * N_ + m0;
    const int tid = threadIdx.x;
    const int w = tid >> 5, lane = tid & 31;
    const int g = lane >> 2, tg = lane & 3;
    const int mbase = (w >> 2) * 32;
    const int hbase = (w & 3) * 32;
    const long long bN = (long long)b * N_;

    if (tid < 64) {
        s_mx[tid] = g_mx[rbase + tid];
        s_rs[tid] = g_rs[rbase + tid];
        s_es[tid] = g_es[rbase + tid];
    }

    unsigned aBase[2], bBase[2];
#pragma unroll
    for (int mf = 0; mf < 2; mf++)
        aBase[mf] = smem_u32(w_s + (mbase + mf * 16 + (lane & 15)) * 36 + 4 * (lane >> 4));
#pragma unroll
    for (int p = 0; p < 2; p++)
        bBase[p] = smem_u32(sBp + (hbase + (2 * p + (lane >> 4)) * 8 + (lane & 7)) * 36
                                + 4 * ((lane >> 3) & 1));

    {
#pragma unroll
        for (int it = 0; it < 4; it++) {
            int idx = tid + it * 256;
            int c = idx >> 3, kk4 = idx & 7;
            cp16(smem_u32(sBp + c * 36 + kk4 * 4),
                 &g_hTt[(long long)c * ROWS + bN + kk4 * 4]);
        }
        CP_COMMIT();
    }
    __syncthreads();

    float acc[2][4][4];
#pragma unroll
    for (int mf = 0; mf < 2; mf++)
#pragma unroll
        for (int nf = 0; nf < 4; nf++)
#pragma unroll
            for (int t = 0; t < 4; t++) acc[mf][nf][t] = 0.f;

    const int mi = tid >> 2;
    const int nb = (tid & 3) * 8;
    const int gm = m0 + mi;
    const float* arow = adjA + (long long)gm * N_;
    const float* edb  = g_ed + bN;
    const float es = s_es[mi], mxv = s_mx[mi], rs = s_rs[mi];

    for (int it = 0; it < 64; it++) {
        const int n0 = it * 32;
        const int wbuf = (it & 1) * K3_WWORDS;
        {
            float4 a4[2], e4[2];
            a4[0] = *(const float4*)(arow + n0 + nb);
            a4[1] = *(const float4*)(arow + n0 + nb + 4);
            e4[0] = *(const float4*)(edb  + n0 + nb);
            e4[1] = *(const float4*)(edb  + n0 + nb + 4);
            const float* ap = (const float*)a4;
            const float* ep = (const float*)e4;
#pragma unroll
            for (int jj = 0; jj < 8; jj++) {
                int n = n0 + nb + jj;
                float adj = ap[jj] + (n == gm ? 1.f : 0.f);
                float t = es + ep[jj];
                float lr = fmaxf(t, 0.2f * t);
                float sc = (adj <= 0.f) ? NEG_INF : lr;
                w_s[wbuf + mi * 36 + nb + jj] = f2tf(__expf(sc - mxv) * rs);
            }
        }
        if (it + 1 < 64) {
            const int st = ((it + 1) % 3) * K3_BWORDS;
            const long long gbase = bN + (long long)(it + 1) * 32;
#pragma unroll
            for (int c4 = 0; c4 < 4; c4++) {
                int idx = tid + c4 * 256;
                int c = idx >> 3, kk4 = idx & 7;
                cp16(smem_u32(sBp + st + c * 36 + kk4 * 4),
                     &g_hTt[(long long)c * ROWS + gbase + kk4 * 4]);
            }
        }
        CP_COMMIT();
        CP_WAIT1();
        __syncthreads();

        const unsigned aOff = (unsigned)(it & 1) * (K3_WWORDS * 4);
        const unsigned bOff = (unsigned)(it % 3) * (K3_BWORDS * 4);
#pragma unroll
        for (int ks = 0; ks < 4; ks++) {
            unsigned afr[2][4], bfr[4][2];
            ldm_x4(afr[0][0], afr[0][1], afr[0][2], afr[0][3], aBase[0] + aOff + ks * 32);
            ldm_x4(afr[1][0], afr[1][1], afr[1][2], afr[1][3], aBase[1] + aOff + ks * 32);
            ldm_x4(bfr[0][0], bfr[0][1], bfr[1][0], bfr[1][1], bBase[0] + bOff + ks * 32);
            ldm_x4(bfr[2][0], bfr[2][1], bfr[3][0], bfr[3][1], bBase[1] + bOff + ks * 32);
#pragma unroll
            for (int mf = 0; mf < 2; mf++)
#pragma unroll
                for (int nf = 0; nf < 4; nf++)
                    mma8(acc[mf][nf], afr[mf], bfr[nf]);
        }
    }

    // ---- fused fc2 GEMM ----
    __syncthreads();
    unsigned* sHP = dyn3;            // [64][132]
    unsigned* sFW = dyn3 + 64 * 132; // [64][132]

#pragma unroll
    for (int mf = 0; mf < 2; mf++) {
#pragma unroll
        for (int nf = 0; nf < 4; nf++) {
            int c = hbase + nf * 8 + 2 * tg;
            int r0l = mbase + mf * 16 + g;
            int r1l = r0l + 8;
            float v0 = acc[mf][nf][0], v1 = acc[mf][nf][1];
            float v2 = acc[mf][nf][2], v3 = acc[mf][nf][3];
            v0 = v0 > 0.f ? v0 : expm1f(v0);
            v1 = v1 > 0.f ? v1 : expm1f(v1);
            v2 = v2 > 0.f ? v2 : expm1f(v2);
            v3 = v3 > 0.f ? v3 : expm1f(v3);
            sHP[r0l * 132 + c]     = f2tf(v0);
            sHP[r0l * 132 + c + 1] = f2tf(v1);
            sHP[r1l * 132 + c]     = f2tf(v2);
            sHP[r1l * 132 + c + 1] = f2tf(v3);
        }
    }
#pragma unroll
    for (int it = 0; it < 8; it++) {
        int idx = tid + it * 256;
        int o = idx >> 5, k4 = idx & 31;
        float4 v = *(const float4*)&fc2w[o * H_ + k4 * 4];
        uint4 u = { f2tf(v.x), f2tf(v.y), f2tf(v.z), f2tf(v.w) };
        *(uint4*)&sFW[o * 132 + k4 * 4] = u;
    }
    __syncthreads();

    const int mbase2 = (w >> 2) * 32;
    const int obase2 = (w & 3) * 16;
    unsigned aB2[2];
#pragma unroll
    for (int mf = 0; mf < 2; mf++)
        aB2[mf] = smem_u32(sHP + (mbase2 + mf * 16 + (lane & 15)) * 132 + 4 * (lane >> 4));
    unsigned bB2 = smem_u32(sFW + (obase2 + (lane >> 4) * 8 + (lane & 7)) * 132
                                + 4 * ((lane >> 3) & 1));

    float acc2[2][2][4];
#pragma unroll
    for (int mf = 0; mf < 2; mf++)
#pragma unroll
        for (int nf = 0; nf < 2; nf++)
#pragma unroll
            for (int t = 0; t < 4; t++) acc2[mf][nf][t] = 0.f;

#pragma unroll
    for (int ks = 0; ks < 16; ks++) {
        unsigned afr[2][4], bfr[2][2];
        ldm_x4(afr[0][0], afr[0][1], afr[0][2], afr[0][3], aB2[0] + ks * 32);
        ldm_x4(afr[1][0], afr[1][1], afr[1][2], afr[1][3], aB2[1] + ks * 32);
        ldm_x4(bfr[0][0], bfr[0][1], bfr[1][0], bfr[1][1], bB2 + ks * 32);
#pragma unroll
        for (int mf = 0; mf < 2; mf++)
#pragma unroll
            for (int nf = 0; nf < 2; nf++)
                mma8(acc2[mf][nf], afr[mf], bfr[nf]);
    }

#pragma unroll
    for (int mf = 0; mf < 2; mf++) {
#pragma unroll
        for (int nf = 0; nf < 2; nf++) {
            int c = obase2 + nf * 8 + 2 * tg;
            int r0 = rbase + mbase2 + mf * 16 + g;
            int r1 = r0 + 8;
            float b0 = fc2b[c], b1 = fc2b[c + 1];
            float w0 = Wa[c],   w1 = Wa[c + 1];
            float v0 = acc2[mf][nf][0] + b0, v1 = acc2[mf][nf][1] + b1;
            float v2 = acc2[mf][nf][2] + b0, v3 = acc2[mf][nf][3] + b1;
            *(float2*)&out[OFF_XPROJ + (long long)r0 * O_ + c] = make_float2(v0, v1);
            *(float2*)&out[OFF_XPROJ + (long long)r1 * O_ + c] = make_float2(v2, v3);
            g_xpwTt[(long long)c       * ROWS + r0] = f2tf(v0 + w0);
            g_xpwTt[(long long)(c + 1) * ROWS + r0] = f2tf(v1 + w1);
            g_xpwTt[(long long)c       * ROWS + r1] = f2tf(v2 + w0);
            g_xpwTt[(long long)(c + 1) * ROWS + r1] = f2tf(v3 + w1);
        }
    }
}

// ---------------------------------------------------------------------------
// K5: logits = x_proj - A1^T @ xpw -- 64m x 64o blocks (grid 256, smem 55KB).
// Warp tile 32m x 16o (8 warps = 2m x 4o). 3-stage cp.async, 1 sync/iter.
// ---------------------------------------------------------------------------
constexpr int K5_AWORDS = 64 * 36;            // 2304
constexpr int K5_BWORDS = 64 * 36;            // 2304
constexpr int K5_SMEM   = (3 * K5_AWORDS + 3 * K5_BWORDS) * 4;   // 55296 B

__global__ __launch_bounds__(256) void k5_logits(float* __restrict__ out)
{
    extern __shared__ unsigned dyn5[];
    unsigned* sAp = dyn5;
    unsigned* sBp = dyn5 + 3 * K5_AWORDS;

    const int b  = blockIdx.x >> 5;
    const int m0 = (blockIdx.x & 31) * 64;
    const int tid = threadIdx.x;
    const int w = tid >> 5, lane = tid & 31;
    const int g = lane >> 2, tg = lane & 3;
    const int mbase = (w >> 2) * 32;      // 0 or 32
    const int obase = (w & 3) * 16;       // 0,16,32,48
    const long long bN = (long long)b * N_;

    unsigned aBase[2], bBase;
#pragma unroll
    for (int mf = 0; mf < 2; mf++)
        aBase[mf] = smem_u32(sAp + (mbase + mf * 16 + (lane & 15)) * 36 + 4 * (lane >> 4));
    bBase = smem_u32(sBp + (obase + (lane >> 4) * 8 + (lane & 7)) * 36
                         + 4 * ((lane >> 3) & 1));

    // prefetch tile 0
    {
#pragma unroll
        for (int c4 = 0; c4 < 2; c4++) {
            int idx = tid + c4 * 256;          // 512 float4
            int m = idx >> 3, kk4 = idx & 7;
            cp16(smem_u32(sAp + m * 36 + kk4 * 4),
                 &g_A1T[(long long)(m0 + m) * N_ + kk4 * 4]);
        }
#pragma unroll
        for (int c4 = 0; c4 < 2; c4++) {
            int idx = tid + c4 * 256;
            int o = idx >> 3, kk4 = idx & 7;
            cp16(smem_u32(sBp + o * 36 + kk4 * 4),
                 &g_xpwTt[(long long)o * ROWS + bN + kk4 * 4]);
        }
        CP_COMMIT();
    }

    float acc[2][2][4];
#pragma unroll
    for (int mf = 0; mf < 2; mf++)
#pragma unroll
        for (int nf = 0; nf < 2; nf++)
#pragma unroll
            for (int t = 0; t < 4; t++) acc[mf][nf][t] = 0.f;

    for (int it = 0; it < 64; it++) {
        if (it + 1 < 64) {
            const int stA = ((it + 1) % 3) * K5_AWORDS;
            const int stB = ((it + 1) % 3) * K5_BWORDS;
            const int n1 = (it + 1) * 32;
#pragma unroll
            for (int c4 = 0; c4 < 2; c4++) {
                int idx = tid + c4 * 256;
                int m = idx >> 3, kk4 = idx & 7;
                cp16(smem_u32(sAp + stA + m * 36 + kk4 * 4),
                     &g_A1T[(long long)(m0 + m) * N_ + n1 + kk4 * 4]);
            }
#pragma unroll
            for (int c4 = 0; c4 < 2; c4++) {
                int idx = tid + c4 * 256;
                int o = idx >> 3, kk4 = idx & 7;
                cp16(smem_u32(sBp + stB + o * 36 + kk4 * 4),
                     &g_xpwTt[(long long)o * ROWS + bN + n1 + kk4 * 4]);
            }
        }
        CP_COMMIT();
        CP_WAIT1();
        __syncthreads();

        const unsigned aOff = (unsigned)(it % 3) * (K5_AWORDS * 4);
        const unsigned bOff = (unsigned)(it % 3) * (K5_BWORDS * 4);
#pragma unroll
        for (int ks = 0; ks < 4; ks++) {
            unsigned afr[2][4], bfr[2][2];
            ldm_x4(afr[0][0], afr[0][1], afr[0][2], afr[0][3], aBase[0] + aOff + ks * 32);
            ldm_x4(afr[1][0], afr[1][1], afr[1][2], afr[1][3], aBase[1] + aOff + ks * 32);
            ldm_x4(bfr[0][0], bfr[0][1], bfr[1][0], bfr[1][1], bBase + bOff + ks * 32);
#pragma unroll
            for (int mf = 0; mf < 2; mf++)
#pragma unroll
                for (int nf = 0; nf < 2; nf++)
                    mma8(acc[mf][nf], afr[mf], bfr[nf]);
        }
    }

#pragma unroll
    for (int mf = 0; mf < 2; mf++) {
#pragma unroll
        for (int nf = 0; nf < 2; nf++) {
            int c = obase + nf * 8 + 2 * tg;
            int r0 = b * N_ + m0 + mbase + mf * 16 + g;
            int r1 = r0 + 8;
            float2 xp0 = *(const float2*)&out[OFF_XPROJ + (long long)r0 * O_ + c];
            float2 xp1 = *(const float2*)&out[OFF_XPROJ + (long long)r1 * O_ + c];
            float2 o0, o1;
            o0.x = xp0.x - acc[mf][nf][0]; o0.y = xp0.y - acc[mf][nf][1];
            o1.x = xp1.x - acc[mf][nf][2]; o1.y = xp1.y - acc[mf][nf][3];
            *(float2*)&out[OFF_LOGITS + (long long)r0 * O_ + c] = o0;
            *(float2*)&out[OFF_LOGITS + (long long)r1 * O_ + c] = o1;
        }
    }
}

// ---------------------------------------------------------------------------
extern "C" void kernel_launch(void* const* d_in, const int* in_sizes, int n_in,
                              void* d_out, int out_size)
{
    const float* x     = (const float*)d_in[0];
    const float* adjA  = (const float*)d_in[1];
    const float* W     = (const float*)d_in[2];
    const float* a_src = (const float*)d_in[3];
    const float* a_dst = (const float*)d_in[4];
    const float* fc2w  = (const float*)d_in[5];
    const float* fc2b  = (const float*)d_in[6];
    const float* Wa    = (const float*)d_in[7];
    const float* z     = (const float*)d_in[8];
    const float* zpos  = (const float*)d_in[9];
    float* out = (float*)d_out;

    cudaFuncSetAttribute(k3_attn,   cudaFuncAttributeMaxDynamicSharedMemorySize, K3_SMEM);
    cudaFuncSetAttribute(k5_logits, cudaFuncAttributeMaxDynamicSharedMemorySize, K5_SMEM);

    k0_misc      <<<(N_ * N_ / 4 + 255) / 256, 256>>>(adjA, zpos, Wa, z, out);
    k0b_transpose<<<64 * 64, 256>>>(out);
    k1_h         <<<ROWS / 64, 256>>>(x, W, a_src, a_dst);
    k2_stats     <<<N_, 256>>>(adjA);
    k3_attn      <<<B_ * (N_ / 64), 256, K3_SMEM>>>(adjA, fc2w, fc2b, Wa, out);
    k5_logits    <<<B_ * (N_ / 64), 256, K5_SMEM>>>(out);
}

// round 16
// speedup vs baseline: 1.2802x; 1.2802x over previous
#include <cuda_runtime.h>
#include <math.h>

// Problem constants
constexpr int B_ = 8, N_ = 2048, F_ = 128, H_ = 128, O_ = 64;
constexpr int ROWS = B_ * N_;            // 16384
constexpr float NEG_INF = -1.0e9f;

// Output layout (tuple flattened in order)
constexpr long long OFF_XPROJ  = 0;
constexpr long long OFF_LOGITS = OFF_XPROJ  + (long long)B_ * N_ * O_;
constexpr long long OFF_ADJ1   = OFF_LOGITS + (long long)B_ * N_ * O_;
constexpr long long OFF_EYE    = OFF_ADJ1   + (long long)N_ * N_;
constexpr long long OFF_Z      = OFF_EYE    + (long long)N_ * N_;
constexpr long long OFF_ZPOS   = OFF_Z      + 1;                    // odd -> 4B only
constexpr long long OFF_ADJA   = OFF_ZPOS   + (long long)N_ * N_;   // odd
constexpr long long OFF_WA     = OFF_ADJA   + (long long)N_ * N_;

// Scratch (device globals). *t arrays hold tf32 bit patterns.
__device__ unsigned g_hTt  [H_ * ROWS];   // tf32(h^T)       (B-operand k3)
__device__ unsigned g_A1T  [N_ * N_];     // tf32(adj_A1^T)  (A-operand k5)
__device__ unsigned g_xpwTt[O_ * ROWS];   // tf32((xp+Wa)^T) (B-operand k5)
__device__ float    g_es   [ROWS];
__device__ float    g_ed   [ROWS];
__device__ float    g_mx   [ROWS];
__device__ float    g_rs   [ROWS];

// ---- helpers --------------------------------------------------------------
__device__ __forceinline__ unsigned f2tf(float f) {
    unsigned u; asm("cvt.rna.tf32.f32 %0, %1;" : "=r"(u) : "f"(f)); return u;
}
__device__ __forceinline__ void mma8(float* d, const unsigned* a, const unsigned* b) {
    asm volatile("mma.sync.aligned.m16n8k8.row.col.f32.tf32.tf32.f32 "
        "{%0,%1,%2,%3},{%4,%5,%6,%7},{%8,%9},{%0,%1,%2,%3};"
        : "+f"(d[0]), "+f"(d[1]), "+f"(d[2]), "+f"(d[3])
        : "r"(a[0]), "r"(a[1]), "r"(a[2]), "r"(a[3]), "r"(b[0]), "r"(b[1]));
}
__device__ __forceinline__ unsigned smem_u32(const void* p) {
    return (unsigned)__cvta_generic_to_shared(p);
}
__device__ __forceinline__ void ldm_x4(unsigned& r0, unsigned& r1,
                                       unsigned& r2, unsigned& r3, unsigned addr) {
    asm volatile("ldmatrix.sync.aligned.m8n8.x4.shared.b16 {%0,%1,%2,%3}, [%4];"
        : "=r"(r0), "=r"(r1), "=r"(r2), "=r"(r3) : "r"(addr));
}
__device__ __forceinline__ void cp16(unsigned dst, const void* src) {
    asm volatile("cp.async.cg.shared.global [%0], [%1], 16;" :: "r"(dst), "l"(src));
}
#define CP_COMMIT() asm volatile("cp.async.commit_group;")
#define CP_WAIT1()  asm volatile("cp.async.wait_group 1;" ::: "memory")

// fast sinh via exp (rel err ~1e-6, fine vs 1e-3 gate)
__device__ __forceinline__ float fast_sinh(float t) {
    float et = __expf(t);
    return 0.5f * (et - __fdividef(1.f, et));
}

// ---------------------------------------------------------------------------
// K0 (fused with old k0b): one 32x32 tile per block.
// adjA tile -> sinh/clip -> adj_A1 store + smem transpose -> g_A1T (tf32);
// plus eye / zpos copy / adjA copy. Scalar coalesced stores (128B/row).
// ---------------------------------------------------------------------------
__global__ __launch_bounds__(256) void k0_misc(const float* __restrict__ adjA,
                                               const float* __restrict__ zpos,
                                               const float* __restrict__ Wa,
                                               const float* __restrict__ z,
                                               float* __restrict__ out)
{
    __shared__ float t[32][33];
    int bx = blockIdx.x;
    int c0 = (bx & 63) * 32;     // col tile
    int r0 = (bx >> 6) * 32;     // row tile
    int tid = threadIdx.x;
    int lr = tid >> 5, lc = tid & 31;

#pragma unroll
    for (int it = 0; it < 4; it++) {
        int row = lr + it * 8;
        long long gidx = (long long)(r0 + row) * N_ + c0 + lc;
        float a = adjA[gidx];
        float zp = zpos[gidx];

        float c = fminf(fmaxf(a, -3.f), 3.f);
        float s = fast_sinh(3.f * c);
        s = fminf(fmaxf(s, -1000.f), 1000.f);
        t[row][lc] = s;

        out[OFF_ADJ1 + gidx] = s;
        out[OFF_EYE  + gidx] = (r0 + row == c0 + lc) ? 1.f : 0.f;
        out[OFF_ZPOS + gidx] = zp;
        out[OFF_ADJA + gidx] = a;
    }
    __syncthreads();
#pragma unroll
    for (int it = 0; it < 4; it++) {
        int row = lr + it * 8;
        g_A1T[(long long)(c0 + row) * N_ + r0 + lc] = f2tf(t[lc][row]);
    }
    if (bx == 0) {
        if (tid < O_)  out[OFF_WA + tid] = Wa[tid];
        if (tid == O_) out[OFF_Z] = z[0];
    }
}

// ---------------------------------------------------------------------------
// K1: h = x @ W^T -- tf32 mma + fused e_src/e_dst reduction.
// ---------------------------------------------------------------------------
__global__ __launch_bounds__(256) void k1_h(const float* __restrict__ x,
                                            const float* __restrict__ W,
                                            const float* __restrict__ a_src,
                                            const float* __restrict__ a_dst)
{
    __shared__ unsigned sA[64][36];
    __shared__ unsigned sB[128][36];
    __shared__ float eps[4][64], epd[4][64];
    const int m0 = blockIdx.x * 64;
    const int tid = threadIdx.x;
    const int w = tid >> 5, lane = tid & 31;
    const int g = lane >> 2, tg = lane & 3;
    const int mbase = (w >> 2) * 32;
    const int hbase = (w & 3) * 32;
    const int hw = w & 3;

    float acc[2][4][4];
#pragma unroll
    for (int mf = 0; mf < 2; mf++)
#pragma unroll
        for (int nf = 0; nf < 4; nf++)
#pragma unroll
            for (int t = 0; t < 4; t++) acc[mf][nf][t] = 0.f;

    for (int f0 = 0; f0 < F_; f0 += 32) {
#pragma unroll
        for (int it = 0; it < 2; it++) {
            int idx = tid + it * 256;
            int mi = idx >> 3, k4 = idx & 7;
            float4 v = *(const float4*)&x[(m0 + mi) * F_ + f0 + k4 * 4];
            uint4 u = { f2tf(v.x), f2tf(v.y), f2tf(v.z), f2tf(v.w) };
            *(uint4*)&sA[mi][k4 * 4] = u;
        }
#pragma unroll
        for (int it = 0; it < 4; it++) {
            int idx = tid + it * 256;
            int hh = idx >> 3, k4 = idx & 7;
            float4 v = *(const float4*)&W[hh * F_ + f0 + k4 * 4];
            uint4 u = { f2tf(v.x), f2tf(v.y), f2tf(v.z), f2tf(v.w) };
            *(uint4*)&sB[hh][k4 * 4] = u;
        }
        __syncthreads();
#pragma unroll
        for (int ks = 0; ks < 4; ks++) {
            int kb = ks * 8;
            unsigned afr[2][4], bfr[4][2];
#pragma unroll
            for (int mf = 0; mf < 2; mf++) {
                int mr = mbase + mf * 16 + g;
                afr[mf][0] = sA[mr    ][kb + tg];
                afr[mf][1] = sA[mr + 8][kb + tg];
                afr[mf][2] = sA[mr    ][kb + 4 + tg];
                afr[mf][3] = sA[mr + 8][kb + 4 + tg];
            }
#pragma unroll
            for (int nf = 0; nf < 4; nf++) {
                int cc = hbase + nf * 8 + g;
                bfr[nf][0] = sB[cc][kb + tg];
                bfr[nf][1] = sB[cc][kb + 4 + tg];
            }
#pragma unroll
            for (int mf = 0; mf < 2; mf++)
#pragma unroll
                for (int nf = 0; nf < 4; nf++)
                    mma8(acc[mf][nf], afr[mf], bfr[nf]);
        }
        __syncthreads();
    }

    float ps[4] = {0.f, 0.f, 0.f, 0.f};
    float pd[4] = {0.f, 0.f, 0.f, 0.f};
#pragma unroll
    for (int mf = 0; mf < 2; mf++) {
#pragma unroll
        for (int nf = 0; nf < 4; nf++) {
            int c = hbase + nf * 8 + 2 * tg;
            int r0 = m0 + mbase + mf * 16 + g;
            int r1 = r0 + 8;
            float v0 = acc[mf][nf][0], v1 = acc[mf][nf][1];
            float v2 = acc[mf][nf][2], v3 = acc[mf][nf][3];
            g_hTt[(long long)c       * ROWS + r0] = f2tf(v0);
            g_hTt[(long long)(c + 1) * ROWS + r0] = f2tf(v1);
            g_hTt[(long long)c       * ROWS + r1] = f2tf(v2);
            g_hTt[(long long)(c + 1) * ROWS + r1] = f2tf(v3);
            float as0 = a_src[c], as1 = a_src[c + 1];
            float ad0 = a_dst[c], ad1 = a_dst[c + 1];
            ps[mf * 2 + 0] += v0 * as0 + v1 * as1;
            ps[mf * 2 + 1] += v2 * as0 + v3 * as1;
            pd[mf * 2 + 0] += v0 * ad0 + v1 * ad1;
            pd[mf * 2 + 1] += v2 * ad0 + v3 * ad1;
        }
    }
#pragma unroll
    for (int off = 1; off <= 2; off <<= 1) {
#pragma unroll
        for (int s = 0; s < 4; s++) {
            ps[s] += __shfl_xor_sync(0xffffffffu, ps[s], off);
            pd[s] += __shfl_xor_sync(0xffffffffu, pd[s], off);
        }
    }
    if (tg == 0) {
#pragma unroll
        for (int s = 0; s < 4; s++) {
            int row = mbase + (s >> 1) * 16 + g + (s & 1) * 8;
            eps[hw][row] = ps[s];
            epd[hw][row] = pd[s];
        }
    }
    __syncthreads();
    if (tid < 64) {
        float s = eps[0][tid] + eps[1][tid] + eps[2][tid] + eps[3][tid];
        float d = epd[0][tid] + epd[1][tid] + epd[2][tid] + epd[3][tid];
        g_es[m0 + tid] = s;
        g_ed[m0 + tid] = d;
    }
}

// ---------------------------------------------------------------------------
// K2: softmax row stats (R14 form: scalar loops, regs ~30).
// Pass 1: masked max of raw ed + count; lrelu post-reduce (monotone).
// Pass 2: exp for unmasked; masked as cnt*exp(NEG_INF-mx).
// ---------------------------------------------------------------------------
__global__ __launch_bounds__(256) void k2_stats(const float* __restrict__ adjA)
{
    __shared__ unsigned char msk[N_];
    const int m = blockIdx.x;
    const int tid = threadIdx.x;
    const int warp = tid >> 5, lane = tid & 31;
#pragma unroll
    for (int it = 0; it < 8; it++) {
        int n = tid + it * 256;
        float adj = adjA[(long long)m * N_ + n] + (n == m ? 1.f : 0.f);
        msk[n] = (adj <= 0.f) ? 1 : 0;
    }
    __syncthreads();

    const int b = warp;
    const int r = b * N_ + m;
    const float es = g_es[r];
    const float* edb = g_ed + b * N_;

    float mxe = -INFINITY;
    int cnt = 0;
#pragma unroll 8
    for (int t = 0; t < 64; t++) {
        int n = lane + 32 * t;
        float ed = edb[n];
        int k = msk[n];
        mxe = fmaxf(mxe, k ? -INFINITY : ed);
        cnt += k;
    }
#pragma unroll
    for (int off = 16; off >= 1; off >>= 1) {
        mxe = fmaxf(mxe, __shfl_xor_sync(0xffffffffu, mxe, off));
        cnt += __shfl_xor_sync(0xffffffffu, cnt, off);
    }
    float mx;
    if (mxe == -INFINITY) mx = NEG_INF;
    else { float v = es + mxe; mx = fmaxf(v, 0.2f * v); }

    float sm = 0.f;
#pragma unroll 8
    for (int t = 0; t < 64; t++) {
        int n = lane + 32 * t;
        float v = es + edb[n];
        float lr = fmaxf(v, 0.2f * v);
        float e = __expf(lr - mx);
        sm += msk[n] ? 0.f : e;
    }
#pragma unroll
    for (int off = 16; off >= 1; off >>= 1)
        sm += __shfl_xor_sync(0xffffffffu, sm, off);

    if (lane == 0) {
        sm += (float)cnt * __expf(NEG_INF - mx);
        g_mx[r] = mx;
        g_rs[r] = 1.f / sm;
    }
}

// ---------------------------------------------------------------------------
// K3: hp = elu(attn @ h), then FUSED fc2: x_proj = hp @ fc2w^T + fc2b.
// ---------------------------------------------------------------------------
constexpr int K3_WWORDS = 64 * 36;            // 2304
constexpr int K3_BWORDS = 128 * 36;           // 4608
constexpr int K3_SMEM   = (2 * K3_WWORDS + 3 * K3_BWORDS + 3 * 64) * 4;  // 74496 B

__global__ __launch_bounds__(256) void k3_attn(const float* __restrict__ adjA,
                                               const float* __restrict__ fc2w,
                                               const float* __restrict__ fc2b,
                                               const float* __restrict__ Wa,
                                               float* __restrict__ out)
{
    extern __shared__ unsigned dyn3[];
    unsigned* w_s = dyn3;                       // 2 bufs
    unsigned* sBp = dyn3 + 2 * K3_WWORDS;       // 3 stages
    float* s_mx = (float*)(dyn3 + 2 * K3_WWORDS + 3 * K3_BWORDS);
    float* s_rs = s_mx + 64;
    float* s_es = s_rs + 64;

    const int b  = blockIdx.x >> 5;
    const int m0 = (blockIdx.x & 31) * 64;
    const int rbase = b * N_ + m0;
    const int tid = threadIdx.x;
    const int w = tid >> 5, lane = tid & 31;
    const int g = lane >> 2, tg = lane & 3;
    const int mbase = (w >> 2) * 32;
    const int hbase = (w & 3) * 32;
    const long long bN = (long long)b * N_;

    if (tid < 64) {
        s_mx[tid] = g_mx[rbase + tid];
        s_rs[tid] = g_rs[rbase + tid];
        s_es[tid] = g_es[rbase + tid];
    }

    unsigned aBase[2], bBase[2];
#pragma unroll
    for (int mf = 0; mf < 2; mf++)
        aBase[mf] = smem_u32(w_s + (mbase + mf * 16 + (lane & 15)) * 36 + 4 * (lane >> 4));
#pragma unroll
    for (int p = 0; p < 2; p++)
        bBase[p] = smem_u32(sBp + (hbase + (2 * p + (lane >> 4)) * 8 + (lane & 7)) * 36
                                + 4 * ((lane >> 3) & 1));

    {
#pragma unroll
        for (int it = 0; it < 4; it++) {
            int idx = tid + it * 256;
            int c = idx >> 3, kk4 = idx & 7;
            cp16(smem_u32(sBp + c * 36 + kk4 * 4),
                 &g_hTt[(long long)c * ROWS + bN + kk4 * 4]);
        }
        CP_COMMIT();
    }
    __syncthreads();

    float acc[2][4][4];
#pragma unroll
    for (int mf = 0; mf < 2; mf++)
#pragma unroll
        for (int nf = 0; nf < 4; nf++)
#pragma unroll
            for (int t = 0; t < 4; t++) acc[mf][nf][t] = 0.f;

    const int mi = tid >> 2;
    const int nb = (tid & 3) * 8;
    const int gm = m0 + mi;
    const float* arow = adjA + (long long)gm * N_;
    const float* edb  = g_ed + bN;
    const float es = s_es[mi], mxv = s_mx[mi], rs = s_rs[mi];

    for (int it = 0; it < 64; it++) {
        const int n0 = it * 32;
        const int wbuf = (it & 1) * K3_WWORDS;
        {
            float4 a4[2], e4[2];
            a4[0] = *(const float4*)(arow + n0 + nb);
            a4[1] = *(const float4*)(arow + n0 + nb + 4);
            e4[0] = *(const float4*)(edb  + n0 + nb);
            e4[1] = *(const float4*)(edb  + n0 + nb + 4);
            const float* ap = (const float*)a4;
            const float* ep = (const float*)e4;
#pragma unroll
            for (int jj = 0; jj < 8; jj++) {
                int n = n0 + nb + jj;
                float adj = ap[jj] + (n == gm ? 1.f : 0.f);
                float t = es + ep[jj];
                float lr = fmaxf(t, 0.2f * t);
                float sc = (adj <= 0.f) ? NEG_INF : lr;
                w_s[wbuf + mi * 36 + nb + jj] = f2tf(__expf(sc - mxv) * rs);
            }
        }
        if (it + 1 < 64) {
            const int st = ((it + 1) % 3) * K3_BWORDS;
            const long long gbase = bN + (long long)(it + 1) * 32;
#pragma unroll
            for (int c4 = 0; c4 < 4; c4++) {
                int idx = tid + c4 * 256;
                int c = idx >> 3, kk4 = idx & 7;
                cp16(smem_u32(sBp + st + c * 36 + kk4 * 4),
                     &g_hTt[(long long)c * ROWS + gbase + kk4 * 4]);
            }
        }
        CP_COMMIT();
        CP_WAIT1();
        __syncthreads();

        const unsigned aOff = (unsigned)(it & 1) * (K3_WWORDS * 4);
        const unsigned bOff = (unsigned)(it % 3) * (K3_BWORDS * 4);
#pragma unroll
        for (int ks = 0; ks < 4; ks++) {
            unsigned afr[2][4], bfr[4][2];
            ldm_x4(afr[0][0], afr[0][1], afr[0][2], afr[0][3], aBase[0] + aOff + ks * 32);
            ldm_x4(afr[1][0], afr[1][1], afr[1][2], afr[1][3], aBase[1] + aOff + ks * 32);
            ldm_x4(bfr[0][0], bfr[0][1], bfr[1][0], bfr[1][1], bBase[0] + bOff + ks * 32);
            ldm_x4(bfr[2][0], bfr[2][1], bfr[3][0], bfr[3][1], bBase[1] + bOff + ks * 32);
#pragma unroll
            for (int mf = 0; mf < 2; mf++)
#pragma unroll
                for (int nf = 0; nf < 4; nf++)
                    mma8(acc[mf][nf], afr[mf], bfr[nf]);
        }
    }

    // ---- fused fc2 GEMM ----
    __syncthreads();
    unsigned* sHP = dyn3;            // [64][132]
    unsigned* sFW = dyn3 + 64 * 132; // [64][132]

#pragma unroll
    for (int mf = 0; mf < 2; mf++) {
#pragma unroll
        for (int nf = 0; nf < 4; nf++) {
            int c = hbase + nf * 8 + 2 * tg;
            int r0l = mbase + mf * 16 + g;
            int r1l = r0l + 8;
            float v0 = acc[mf][nf][0], v1 = acc[mf][nf][1];
            float v2 = acc[mf][nf][2], v3 = acc[mf][nf][3];
            v0 = v0 > 0.f ? v0 : expm1f(v0);
            v1 = v1 > 0.f ? v1 : expm1f(v1);
            v2 = v2 > 0.f ? v2 : expm1f(v2);
            v3 = v3 > 0.f ? v3 : expm1f(v3);
            sHP[r0l * 132 + c]     = f2tf(v0);
            sHP[r0l * 132 + c + 1] = f2tf(v1);
            sHP[r1l * 132 + c]     = f2tf(v2);
            sHP[r1l * 132 + c + 1] = f2tf(v3);
        }
    }
#pragma unroll
    for (int it = 0; it < 8; it++) {
        int idx = tid + it * 256;
        int o = idx >> 5, k4 = idx & 31;
        float4 v = *(const float4*)&fc2w[o * H_ + k4 * 4];
        uint4 u = { f2tf(v.x), f2tf(v.y), f2tf(v.z), f2tf(v.w) };
        *(uint4*)&sFW[o * 132 + k4 * 4] = u;
    }
    __syncthreads();

    const int mbase2 = (w >> 2) * 32;
    const int obase2 = (w & 3) * 16;
    unsigned aB2[2];
#pragma unroll
    for (int mf = 0; mf < 2; mf++)
        aB2[mf] = smem_u32(sHP + (mbase2 + mf * 16 + (lane & 15)) * 132 + 4 * (lane >> 4));
    unsigned bB2 = smem_u32(sFW + (obase2 + (lane >> 4) * 8 + (lane & 7)) * 132
                                + 4 * ((lane >> 3) & 1));

    float acc2[2][2][4];
#pragma unroll
    for (int mf = 0; mf < 2; mf++)
#pragma unroll
        for (int nf = 0; nf < 2; nf++)
#pragma unroll
            for (int t = 0; t < 4; t++) acc2[mf][nf][t] = 0.f;

#pragma unroll
    for (int ks = 0; ks < 16; ks++) {
        unsigned afr[2][4], bfr[2][2];
        ldm_x4(afr[0][0], afr[0][1], afr[0][2], afr[0][3], aB2[0] + ks * 32);
        ldm_x4(afr[1][0], afr[1][1], afr[1][2], afr[1][3], aB2[1] + ks * 32);
        ldm_x4(bfr[0][0], bfr[0][1], bfr[1][0], bfr[1][1], bB2 + ks * 32);
#pragma unroll
        for (int mf = 0; mf < 2; mf++)
#pragma unroll
            for (int nf = 0; nf < 2; nf++)
                mma8(acc2[mf][nf], afr[mf], bfr[nf]);
    }

#pragma unroll
    for (int mf = 0; mf < 2; mf++) {
#pragma unroll
        for (int nf = 0; nf < 2; nf++) {
            int c = obase2 + nf * 8 + 2 * tg;
            int r0 = rbase + mbase2 + mf * 16 + g;
            int r1 = r0 + 8;
            float b0 = fc2b[c], b1 = fc2b[c + 1];
            float w0 = Wa[c],   w1 = Wa[c + 1];
            float v0 = acc2[mf][nf][0] + b0, v1 = acc2[mf][nf][1] + b1;
            float v2 = acc2[mf][nf][2] + b0, v3 = acc2[mf][nf][3] + b1;
            *(float2*)&out[OFF_XPROJ + (long long)r0 * O_ + c] = make_float2(v0, v1);
            *(float2*)&out[OFF_XPROJ + (long long)r1 * O_ + c] = make_float2(v2, v3);
            g_xpwTt[(long long)c       * ROWS + r0] = f2tf(v0 + w0);
            g_xpwTt[(long long)(c + 1) * ROWS + r0] = f2tf(v1 + w1);
            g_xpwTt[(long long)c       * ROWS + r1] = f2tf(v2 + w0);
            g_xpwTt[(long long)(c + 1) * ROWS + r1] = f2tf(v3 + w1);
        }
    }
}

// ---------------------------------------------------------------------------
// K5: logits = x_proj - A1^T @ xpw -- tf32 mma + ldmatrix + cp.async.
// (R14 form: 128m x 64o blocks, grid 128.)
// ---------------------------------------------------------------------------
constexpr int K5_AWORDS = 128 * 36;           // 4608
constexpr int K5_BWORDS = 64 * 36;            // 2304
constexpr int K5_SMEM   = (3 * K5_AWORDS + 3 * K5_BWORDS) * 4;   // 82944 B

__global__ __launch_bounds__(256) void k5_logits(float* __restrict__ out)
{
    extern __shared__ unsigned dyn5[];
    unsigned* sAp = dyn5;
    unsigned* sBp = dyn5 + 3 * K5_AWORDS;

    const int b  = blockIdx.x >> 4;
    const int m0 = (blockIdx.x & 15) * 128;
    const int tid = threadIdx.x;
    const int w = tid >> 5, lane = tid & 31;
    const int g = lane >> 2, tg = lane & 3;
    const int mbase = (w >> 1) * 32;
    const int obase = (w & 1) * 32;
    const long long bN = (long long)b * N_;

    unsigned aBase[2], bBase[2];
#pragma unroll
    for (int mf = 0; mf < 2; mf++)
        aBase[mf] = smem_u32(sAp + (mbase + mf * 16 + (lane & 15)) * 36 + 4 * (lane >> 4));
#pragma unroll
    for (int p = 0; p < 2; p++)
        bBase[p] = smem_u32(sBp + (obase + (2 * p + (lane >> 4)) * 8 + (lane & 7)) * 36
                                + 4 * ((lane >> 3) & 1));

    {
#pragma unroll
        for (int c4 = 0; c4 < 4; c4++) {
            int idx = tid + c4 * 256;
            int m = idx >> 3, kk4 = idx & 7;
            cp16(smem_u32(sAp + m * 36 + kk4 * 4),
                 &g_A1T[(long long)(m0 + m) * N_ + kk4 * 4]);
        }
#pragma unroll
        for (int c4 = 0; c4 < 2; c4++) {
            int idx = tid + c4 * 256;
            int o = idx >> 3, kk4 = idx & 7;
            cp16(smem_u32(sBp + o * 36 + kk4 * 4),
                 &g_xpwTt[(long long)o * ROWS + bN + kk4 * 4]);
        }
        CP_COMMIT();
    }

    float acc[2][4][4];
#pragma unroll
    for (int mf = 0; mf < 2; mf++)
#pragma unroll
        for (int nf = 0; nf < 4; nf++)
#pragma unroll
            for (int t = 0; t < 4; t++) acc[mf][nf][t] = 0.f;

    for (int it = 0; it < 64; it++) {
        if (it + 1 < 64) {
            const int stA = ((it + 1) % 3) * K5_AWORDS;
            const int stB = ((it + 1) % 3) * K5_BWORDS;
            const int n1 = (it + 1) * 32;
#pragma unroll
            for (int c4 = 0; c4 < 4; c4++) {
                int idx = tid + c4 * 256;
                int m = idx >> 3, kk4 = idx & 7;
                cp16(smem_u32(sAp + stA + m * 36 + kk4 * 4),
                     &g_A1T[(long long)(m0 + m) * N_ + n1 + kk4 * 4]);
            }
#pragma unroll
            for (int c4 = 0; c4 < 2; c4++) {
                int idx = tid + c4 * 256;
                int o = idx >> 3, kk4 = idx & 7;
                cp16(smem_u32(sBp + stB + o * 36 + kk4 * 4),
                     &g_xpwTt[(long long)o * ROWS + bN + n1 + kk4 * 4]);
            }
        }
        CP_COMMIT();
        CP_WAIT1();
        __syncthreads();

        const unsigned aOff = (unsigned)(it % 3) * (K5_AWORDS * 4);
        const unsigned bOff = (unsigned)(it % 3) * (K5_BWORDS * 4);
#pragma unroll
        for (int ks = 0; ks < 4; ks++) {
            unsigned afr[2][4], bfr[4][2];
            ldm_x4(afr[0][0], afr[0][1], afr[0][2], afr[0][3], aBase[0] + aOff + ks * 32);
            ldm_x4(afr[1][0], afr[1][1], afr[1][2], afr[1][3], aBase[1] + aOff + ks * 32);
            ldm_x4(bfr[0][0], bfr[0][1], bfr[1][0], bfr[1][1], bBase[0] + bOff + ks * 32);
            ldm_x4(bfr[2][0], bfr[2][1], bfr[3][0], bfr[3][1], bBase[1] + bOff + ks * 32);
#pragma unroll
            for (int mf = 0; mf < 2; mf++)
#pragma unroll
                for (int nf = 0; nf < 4; nf++)
                    mma8(acc[mf][nf], afr[mf], bfr[nf]);
        }
    }

#pragma unroll
    for (int mf = 0; mf < 2; mf++) {
#pragma unroll
        for (int nf = 0; nf < 4; nf++) {
            int c = obase + nf * 8 + 2 * tg;
            int r0 = b * N_ + m0 + mbase + mf * 16 + g;
            int r1 = r0 + 8;
            float2 xp0 = *(const float2*)&out[OFF_XPROJ + (long long)r0 * O_ + c];
            float2 xp1 = *(const float2*)&out[OFF_XPROJ + (long long)r1 * O_ + c];
            float2 o0, o1;
            o0.x = xp0.x - acc[mf][nf][0]; o0.y = xp0.y - acc[mf][nf][1];
            o1.x = xp1.x - acc[mf][nf][2]; o1.y = xp1.y - acc[mf][nf][3];
            *(float2*)&out[OFF_LOGITS + (long long)r0 * O_ + c] = o0;
            *(float2*)&out[OFF_LOGITS + (long long)r1 * O_ + c] = o1;
        }
    }
}

// ---------------------------------------------------------------------------
extern "C" void kernel_launch(void* const* d_in, const int* in_sizes, int n_in,
                              void* d_out, int out_size)
{
    const float* x     = (const float*)d_in[0];
    const float* adjA  = (const float*)d_in[1];
    const float* W     = (const float*)d_in[2];
    const float* a_src = (const float*)d_in[3];
    const float* a_dst = (const float*)d_in[4];
    const float* fc2w  = (const float*)d_in[5];
    const float* fc2b  = (const float*)d_in[6];
    const float* Wa    = (const float*)d_in[7];
    const float* z     = (const float*)d_in[8];
    const float* zpos  = (const float*)d_in[9];
    float* out = (float*)d_out;

    cudaFuncSetAttribute(k3_attn,   cudaFuncAttributeMaxDynamicSharedMemorySize, K3_SMEM);
    cudaFuncSetAttribute(k5_logits, cudaFuncAttributeMaxDynamicSharedMemorySize, K5_SMEM);

    k0_misc   <<<64 * 64, 256>>>(adjA, zpos, Wa, z, out);
    k1_h      <<<ROWS / 64, 256>>>(x, W, a_src, a_dst);
    k2_stats  <<<N_, 256>>>(adjA);
    k3_attn   <<<B_ * (N_ / 64), 256, K3_SMEM>>>(adjA, fc2w, fc2b, Wa, out);
    k5_logits <<<B_ * (N_ / 128), 256, K5_SMEM>>>(out);
}